// round 3
// baseline (speedup 1.0000x reference)
#include <cuda_runtime.h>
#include <cstdint>

#define NHEADS 32
#define NKVH 8
#define HDIM 128
#define BLK_SZ 16
#define DKV (NKVH * HDIM)        /* 1024 floats per token row */
#define MAX_BPS 128
#define SCALE_F 0.08838834764831845f

// ---------------- cp.async helpers ----------------
__device__ __forceinline__ uint32_t smem_u32(const void* p) {
    return (uint32_t)__cvta_generic_to_shared(p);
}
__device__ __forceinline__ void cp16(uint32_t s, const void* g) {
    asm volatile("cp.async.cg.shared.global [%0], [%1], 16;\n" :: "r"(s), "l"(g));
}
__device__ __forceinline__ void cp_commit() {
    asm volatile("cp.async.commit_group;\n");
}
template <int N>
__device__ __forceinline__ void cp_wait() {
    asm volatile("cp.async.wait_group %0;\n" :: "n"(N));
}

// ---------------- scatter new K/V tokens into paged cache ----------------
__global__ void scatter_kv_kernel(const float* __restrict__ k,
                                  const float* __restrict__ v,
                                  float* __restrict__ kc,
                                  float* __restrict__ vc,
                                  const int* __restrict__ slot_mapping,
                                  int total_slots) {
    int b = blockIdx.x;
    int slot = slot_mapping[b];
    if (slot < 0 || slot >= total_slots) return;  // mode="drop"
    const float4* ks = (const float4*)(k + (size_t)b * DKV);
    const float4* vs = (const float4*)(v + (size_t)b * DKV);
    float4* kd = (float4*)(kc + (size_t)slot * DKV);
    float4* vd = (float4*)(vc + (size_t)slot * DKV);
    for (int i = threadIdx.x; i < DKV / 4; i += blockDim.x) {
        kd[i] = ks[i];
        vd[i] = vs[i];
    }
}

// ---------------- decode paged attention ----------------
// grid: (NKVH, BATCH), 256 threads.
// Streams the sequence in 16-token cache blocks with cp.async double buffer.
__global__ void __launch_bounds__(256, 2)
attn_kernel(const float* __restrict__ q,
            const float* __restrict__ kc,
            const float* __restrict__ vc,
            const int* __restrict__ block_tables,
            const int* __restrict__ context_lens,
            float* __restrict__ out) {
    __shared__ float k_s[2][BLK_SZ][HDIM];
    __shared__ float v_s[2][BLK_SZ][HDIM];
    __shared__ float s_s[64];     // raw scores [g][t]
    __shared__ float p_s[64];     // probabilities [g][t]
    __shared__ float sc_s[4];     // per-g rescale for this block
    __shared__ float l_s[4];      // final softmax denominators

    const int kvh = blockIdx.x;
    const int b = blockIdx.y;
    const int tid = threadIdx.x;
    const int lane = tid & 31;
    const int w = tid >> 5;
    const int ctx = context_lens[b];
    const int nblk = (ctx + BLK_SZ - 1) >> 4;
    const int* btab = block_tables + b * MAX_BPS;

    // ---- QK: lane owns dims [lane*4, lane*4+4) for all 4 grouped heads ----
    float4 q4[4];
#pragma unroll
    for (int g = 0; g < 4; ++g) {
        float4 f = *(const float4*)(q + ((size_t)(b * NHEADS + kvh * 4 + g)) * HDIM + lane * 4);
        q4[g] = make_float4(f.x * SCALE_F, f.y * SCALE_F, f.z * SCALE_F, f.w * SCALE_F);
    }

    // ---- PV: thread owns head-group gp and output dims (2u, 2u+1) ----
    const int gp = tid >> 6;
    const int u = tid & 63;
    float2 acc = make_float2(0.f, 0.f);

    // online softmax state (live only in tid<64 threads)
    float m = -1e30f, l = 0.f;

    auto load_tile = [&](int buf, int bid) {
        const float* kb = kc + (size_t)bid * BLK_SZ * DKV + (size_t)kvh * HDIM;
        const float* vb = vc + (size_t)bid * BLK_SZ * DKV + (size_t)kvh * HDIM;
#pragma unroll
        for (int r = 0; r < 2; ++r) {
            int idx = tid + r * 256;        // 0..511 float4 units
            int tok = idx >> 5;             // token within block
            int c4 = idx & 31;              // float4 column
            cp16(smem_u32(&k_s[buf][tok][c4 * 4]), kb + (size_t)tok * DKV + c4 * 4);
            cp16(smem_u32(&v_s[buf][tok][c4 * 4]), vb + (size_t)tok * DKV + c4 * 4);
        }
    };

    load_tile(0, btab[0]);
    cp_commit();

    for (int blk = 0; blk < nblk; ++blk) {
        int nxt = (blk + 1 < nblk) ? blk + 1 : blk;  // clamp (harmless extra load on last iter)
        load_tile((blk + 1) & 1, btab[nxt]);
        cp_commit();
        cp_wait<1>();     // current block's tile is resident
        __syncthreads();

        const int buf = blk & 1;

        // ---- QK scores: warp w handles tokens 2w, 2w+1 ----
#pragma unroll
        for (int r = 0; r < 2; ++r) {
            int t = w * 2 + r;
            float4 kv = *(const float4*)&k_s[buf][t][lane * 4];
            float sg[4];
#pragma unroll
            for (int g = 0; g < 4; ++g)
                sg[g] = kv.x * q4[g].x + kv.y * q4[g].y + kv.z * q4[g].z + kv.w * q4[g].w;
#pragma unroll
            for (int off = 16; off > 0; off >>= 1) {
#pragma unroll
                for (int g = 0; g < 4; ++g)
                    sg[g] += __shfl_xor_sync(0xffffffffu, sg[g], off);
            }
            if (lane < 4) s_s[lane * 16 + t] = sg[lane];
        }
        __syncthreads();

        // ---- online softmax (64 threads; groups of 16 lanes per head-group) ----
        if (tid < 64) {
            int tt = tid & 15;
            float sv = s_s[tid];
            if ((blk << 4) + tt >= ctx) sv = -1e30f;
            float bm = sv;
#pragma unroll
            for (int off = 8; off > 0; off >>= 1)
                bm = fmaxf(bm, __shfl_xor_sync(0xffffffffu, bm, off));
            float mn = fmaxf(m, bm);
            float scale = __expf(m - mn);
            float p = __expf(sv - mn);
            float ps = p;
#pragma unroll
            for (int off = 8; off > 0; off >>= 1)
                ps += __shfl_xor_sync(0xffffffffu, ps, off);
            m = mn;
            l = l * scale + ps;
            p_s[tid] = p;
            if (tt == 0) sc_s[tid >> 4] = scale;
        }
        __syncthreads();

        // ---- PV accumulate ----
        float scale = sc_s[gp];
        acc.x *= scale;
        acc.y *= scale;
#pragma unroll
        for (int t = 0; t < BLK_SZ; ++t) {
            float p = p_s[gp * 16 + t];
            float2 v2 = *(const float2*)&v_s[buf][t][u * 2];
            acc.x += p * v2.x;
            acc.y += p * v2.y;
        }
        __syncthreads();   // protect buffers / p_s before next iter overwrites
    }

    if (tid < 64 && (tid & 15) == 0) l_s[tid >> 4] = l;
    __syncthreads();

    float inv = 1.0f / l_s[gp];
    float* op = out + ((size_t)(b * NHEADS + kvh * 4 + gp)) * HDIM + u * 2;
    op[0] = acc.x * inv;
    op[1] = acc.y * inv;
}

// ---------------- launch ----------------
extern "C" void kernel_launch(void* const* d_in, const int* in_sizes, int n_in,
                              void* d_out, int out_size) {
    const float* q = (const float*)d_in[0];
    const float* k = (const float*)d_in[1];
    const float* v = (const float*)d_in[2];
    float* kc = (float*)d_in[3];   // mutated in place (idempotent scatter, matches reference)
    float* vc = (float*)d_in[4];
    const int* slot_mapping = (const int*)d_in[5];
    const int* block_tables = (const int*)d_in[6];
    const int* context_lens = (const int*)d_in[7];
    float* out = (float*)d_out;

    int total_slots = in_sizes[3] / DKV;  // num_blocks * block_size

    scatter_kv_kernel<<<32, 256>>>(k, v, kc, vc, slot_mapping, total_slots);

    dim3 grid(NKVH, 32);
    attn_kernel<<<grid, 256>>>(q, kc, vc, block_tables, context_lens, out);
}

// round 5
// speedup vs baseline: 1.7305x; 1.7305x over previous
#include <cuda_runtime.h>
#include <cstdint>

#define NHEADS 32
#define NKVH 8
#define HDIM 128
#define BLK_SZ 16
#define DKV (NKVH * HDIM)        /* 1024 floats per token row */
#define MAX_BPS 128
#define BATCH 32
#define SCALE_F 0.08838834764831845f

#define CHUNK_BLKS 16            /* cache blocks per split CTA (256 tokens) */
#define NSPLIT 8                 /* MAX_BPS / CHUNK_BLKS */

// ---------------- split-K scratch (device globals; no allocation) ----------
__device__ float g_pout[(size_t)BATCH * NKVH * 4 * NSPLIT * HDIM]; // 4 MB
__device__ float g_pml[BATCH * NKVH * 4 * NSPLIT * 2];             // m, l

// ---------------- cp.async helpers ----------------
__device__ __forceinline__ uint32_t smem_u32(const void* p) {
    return (uint32_t)__cvta_generic_to_shared(p);
}
__device__ __forceinline__ void cp16(uint32_t s, const void* g) {
    asm volatile("cp.async.cg.shared.global [%0], [%1], 16;\n" :: "r"(s), "l"(g));
}
__device__ __forceinline__ void cp_commit() {
    asm volatile("cp.async.commit_group;\n");
}
template <int N>
__device__ __forceinline__ void cp_wait() {
    asm volatile("cp.async.wait_group %0;\n" :: "n"(N));
}

// ---------------- scatter new K/V tokens into paged cache ----------------
__global__ void scatter_kv_kernel(const float* __restrict__ k,
                                  const float* __restrict__ v,
                                  float* __restrict__ kc,
                                  float* __restrict__ vc,
                                  const int* __restrict__ slot_mapping,
                                  int total_slots) {
    int b = blockIdx.x;
    int slot = slot_mapping[b];
    if (slot < 0 || slot >= total_slots) return;  // mode="drop"
    const float4* ks = (const float4*)(k + (size_t)b * DKV);
    const float4* vs = (const float4*)(v + (size_t)b * DKV);
    float4* kd = (float4*)(kc + (size_t)slot * DKV);
    float4* vd = (float4*)(vc + (size_t)slot * DKV);
    for (int i = threadIdx.x; i < DKV / 4; i += blockDim.x) {
        kd[i] = ks[i];
        vd[i] = vs[i];
    }
}

// ---------------- split-K partial attention ----------------
// grid: (NKVH, BATCH, NSPLIT), 256 threads.
// Each CTA handles up to CHUNK_BLKS cache blocks of one (b, kvh), producing
// unnormalized (m, l, acc) partials.
__global__ void __launch_bounds__(256, 3)
attn_partial_kernel(const float* __restrict__ q,
                    const float* __restrict__ kc,
                    const float* __restrict__ vc,
                    const int* __restrict__ block_tables,
                    const int* __restrict__ context_lens) {
    __shared__ float k_s[2][BLK_SZ][HDIM];
    __shared__ float v_s[2][BLK_SZ][HDIM];
    __shared__ float s_s[64];     // raw scores [g][t]
    __shared__ float p_s[64];     // probabilities [g][t]
    __shared__ float sc_s[4];     // per-g rescale for this block

    const int kvh = blockIdx.x;
    const int b = blockIdx.y;
    const int sp = blockIdx.z;
    const int tid = threadIdx.x;
    const int lane = tid & 31;
    const int w = tid >> 5;

    const int ctx = context_lens[b];
    const int nblk = (ctx + BLK_SZ - 1) >> 4;
    const int blk0 = sp * CHUNK_BLKS;
    if (blk0 >= nblk) return;                       // split has no work
    const int nloc = min(CHUNK_BLKS, nblk - blk0);
    const int* btab = block_tables + b * MAX_BPS + blk0;

    // ---- QK: lane owns dims [lane*4, lane*4+4) for all 4 grouped heads ----
    float4 q4[4];
#pragma unroll
    for (int g = 0; g < 4; ++g) {
        float4 f = *(const float4*)(q + ((size_t)(b * NHEADS + kvh * 4 + g)) * HDIM + lane * 4);
        q4[g] = make_float4(f.x * SCALE_F, f.y * SCALE_F, f.z * SCALE_F, f.w * SCALE_F);
    }

    // ---- PV: thread owns head-group gp and output dims (2u, 2u+1) ----
    const int gp = tid >> 6;
    const int u = tid & 63;
    float2 acc = make_float2(0.f, 0.f);

    // online softmax state (live only in tid<64 threads)
    float m = -1e30f, l = 0.f;

    auto load_tile = [&](int buf, int bid) {
        const float* kb = kc + (size_t)bid * BLK_SZ * DKV + (size_t)kvh * HDIM;
        const float* vb = vc + (size_t)bid * BLK_SZ * DKV + (size_t)kvh * HDIM;
#pragma unroll
        for (int r = 0; r < 2; ++r) {
            int idx = tid + r * 256;        // 0..511 float4 units
            int tok = idx >> 5;             // token within block
            int c4 = idx & 31;              // float4 column
            cp16(smem_u32(&k_s[buf][tok][c4 * 4]), kb + (size_t)tok * DKV + c4 * 4);
            cp16(smem_u32(&v_s[buf][tok][c4 * 4]), vb + (size_t)tok * DKV + c4 * 4);
        }
    };

    load_tile(0, btab[0]);
    cp_commit();

    for (int blk = 0; blk < nloc; ++blk) {
        int nxt = (blk + 1 < nloc) ? blk + 1 : blk;  // clamp (duplicate load on last iter)
        load_tile((blk + 1) & 1, btab[nxt]);
        cp_commit();
        cp_wait<1>();     // current block's tile is resident
        __syncthreads();

        const int buf = blk & 1;

        // ---- QK scores: warp w handles tokens 2w, 2w+1 ----
#pragma unroll
        for (int r = 0; r < 2; ++r) {
            int t = w * 2 + r;
            float4 kv = *(const float4*)&k_s[buf][t][lane * 4];
            float sg[4];
#pragma unroll
            for (int g = 0; g < 4; ++g)
                sg[g] = kv.x * q4[g].x + kv.y * q4[g].y + kv.z * q4[g].z + kv.w * q4[g].w;
#pragma unroll
            for (int off = 16; off > 0; off >>= 1) {
#pragma unroll
                for (int g = 0; g < 4; ++g)
                    sg[g] += __shfl_xor_sync(0xffffffffu, sg[g], off);
            }
            if (lane < 4) s_s[lane * 16 + t] = sg[lane];
        }
        __syncthreads();

        // ---- online softmax (64 threads; 16 lanes per head-group) ----
        if (tid < 64) {
            int tt = tid & 15;
            float sv = s_s[tid];
            if (((blk0 + blk) << 4) + tt >= ctx) sv = -1e30f;
            float bm = sv;
#pragma unroll
            for (int off = 8; off > 0; off >>= 1)
                bm = fmaxf(bm, __shfl_xor_sync(0xffffffffu, bm, off));
            float mn = fmaxf(m, bm);
            float scale = __expf(m - mn);
            float p = __expf(sv - mn);
            float ps = p;
#pragma unroll
            for (int off = 8; off > 0; off >>= 1)
                ps += __shfl_xor_sync(0xffffffffu, ps, off);
            m = mn;
            l = l * scale + ps;
            p_s[tid] = p;
            if (tt == 0) sc_s[tid >> 4] = scale;
        }
        __syncthreads();

        // ---- PV accumulate ----
        float scale = sc_s[gp];
        acc.x *= scale;
        acc.y *= scale;
#pragma unroll
        for (int t = 0; t < BLK_SZ; ++t) {
            float p = p_s[gp * 16 + t];
            float2 v2 = *(const float2*)&v_s[buf][t][u * 2];
            acc.x += p * v2.x;
            acc.y += p * v2.y;
        }
        __syncthreads();   // protect buffers / p_s before next iter overwrites
    }

    // ---- write unnormalized partials ----
    if (tid < 64 && (tid & 15) == 0) {
        int g = tid >> 4;
        int idx = ((b * NKVH + kvh) * 4 + g) * NSPLIT + sp;
        g_pml[idx * 2 + 0] = m;
        g_pml[idx * 2 + 1] = l;
    }
    size_t obase = ((size_t)((b * NKVH + kvh) * 4 + gp) * NSPLIT + sp) * HDIM + u * 2;
    g_pout[obase + 0] = acc.x;
    g_pout[obase + 1] = acc.y;
}

// ---------------- combine split-K partials ----------------
// grid: (NHEADS, BATCH), 128 threads (one per output dim).
__global__ void combine_kernel(const int* __restrict__ context_lens,
                               float* __restrict__ out) {
    const int h = blockIdx.x;
    const int b = blockIdx.y;
    const int d = threadIdx.x;
    const int ctx = context_lens[b];
    const int nblk = (ctx + BLK_SZ - 1) >> 4;
    const int nu = min(NSPLIT, (nblk + CHUNK_BLKS - 1) / CHUNK_BLKS);
    const int kvh = h >> 2;
    const int g = h & 3;
    const int base = ((b * NKVH + kvh) * 4 + g) * NSPLIT;

    float M = -1e30f;
    for (int s = 0; s < nu; ++s)
        M = fmaxf(M, g_pml[(base + s) * 2]);

    float L = 0.f, o = 0.f;
    for (int s = 0; s < nu; ++s) {
        float wgt = __expf(g_pml[(base + s) * 2] - M);
        L += g_pml[(base + s) * 2 + 1] * wgt;
        o += wgt * g_pout[(size_t)(base + s) * HDIM + d];
    }
    out[((size_t)b * NHEADS + h) * HDIM + d] = o / L;
}

// ---------------- launch ----------------
extern "C" void kernel_launch(void* const* d_in, const int* in_sizes, int n_in,
                              void* d_out, int out_size) {
    const float* q = (const float*)d_in[0];
    const float* k = (const float*)d_in[1];
    const float* v = (const float*)d_in[2];
    float* kc = (float*)d_in[3];   // mutated in place (idempotent scatter, matches reference)
    float* vc = (float*)d_in[4];
    const int* slot_mapping = (const int*)d_in[5];
    const int* block_tables = (const int*)d_in[6];
    const int* context_lens = (const int*)d_in[7];
    float* out = (float*)d_out;

    int total_slots = in_sizes[3] / DKV;  // num_blocks * block_size

    scatter_kv_kernel<<<BATCH, 256>>>(k, v, kc, vc, slot_mapping, total_slots);

    dim3 grid(NKVH, BATCH, NSPLIT);
    attn_partial_kernel<<<grid, 256>>>(q, kc, vc, block_tables, context_lens);

    dim3 cgrid(NHEADS, BATCH);
    combine_kernel<<<cgrid, 128>>>(context_lens, out);
}